// round 1
// baseline (speedup 1.0000x reference)
#include <cuda_runtime.h>
#include <cstdint>

#define NH   16
#define DK   64
#define DV   64
#define NB   4
#define NL   512
#define DM   1024
#define BL   (NB*NL)   // 2048

// ---------------- scratch (device globals: allocation-free) ----------------
__device__ float g_qh[NB*NH*NL*DK];   // [b,h,l,dk], pre-scaled by 1/8
__device__ float g_kh[NB*NH*NL*DK];   // [b,h,l,dk]
__device__ float g_vt[NB*NH*DV*NL];   // [b,h,dv,l]  (transposed V)
__device__ float g_ctx[BL*DM];        // [b*l, h*dv]
__device__ float g_out[BL*DM];        // pre-LN output

// ---------------- helpers ----------------
__device__ __forceinline__ unsigned f2tf(float f) {
    unsigned u;
    asm("cvt.rna.tf32.f32 %0, %1;" : "=r"(u) : "f"(f));
    return u;
}

__device__ __forceinline__ void mma_tf32(float* d, const unsigned* a, const unsigned* b) {
    asm volatile(
        "mma.sync.aligned.m16n8k8.row.col.f32.tf32.tf32.f32 "
        "{%0,%1,%2,%3}, {%4,%5,%6,%7}, {%8,%9}, {%0,%1,%2,%3};\n"
        : "+f"(d[0]), "+f"(d[1]), "+f"(d[2]), "+f"(d[3])
        : "r"(a[0]), "r"(a[1]), "r"(a[2]), "r"(a[3]), "r"(b[0]), "r"(b[1]));
}

// ---------------- generic projection GEMM ----------------
// C[2048 x 1024] = A[2048 x 1024] @ W[1024 x 1024] + bias, epilogue by mode:
//  mode 0: q proj  -> g_qh (scaled 0.125)
//  mode 1: k proj  -> g_kh
//  mode 2: v proj  -> g_vt (transposed per head)
//  mode 3: out proj (A = g_ctx) + bias + residual(X) -> g_out
__global__ __launch_bounds__(256) void gemm_kernel(const float* __restrict__ X,
                                                   const float* __restrict__ W,
                                                   const float* __restrict__ bias,
                                                   int mode) {
    __shared__ unsigned As[128][36];   // stride 36 -> conflict-free A-frag loads
    __shared__ unsigned Bs[32][72];    // stride 72 -> conflict-free B-frag loads

    const float* A = (mode == 3) ? g_ctx : X;
    int tid  = threadIdx.x;
    int warp = tid >> 5, lane = tid & 31;
    int wm = warp >> 1, wn = warp & 1;     // 4 x 2 warp grid
    int g  = lane >> 2, tg = lane & 3;
    int m0 = blockIdx.y * 128;
    int n0 = blockIdx.x * 64;

    float acc[2][4][4];
#pragma unroll
    for (int i = 0; i < 2; i++)
#pragma unroll
        for (int j = 0; j < 4; j++)
#pragma unroll
            for (int c = 0; c < 4; c++) acc[i][j][c] = 0.f;

    for (int kb = 0; kb < DM; kb += 32) {
        __syncthreads();
#pragma unroll
        for (int i = 0; i < 16; i++) {
            int e = tid + i * 256;
            int m = e >> 5, kk = e & 31;
            As[m][kk] = f2tf(A[(m0 + m) * DM + kb + kk]);
        }
#pragma unroll
        for (int i = 0; i < 8; i++) {
            int e = tid + i * 256;
            int r = e >> 6, n = e & 63;
            Bs[r][n] = f2tf(W[(kb + r) * DM + n0 + n]);
        }
        __syncthreads();
#pragma unroll
        for (int ks = 0; ks < 4; ks++) {
            unsigned af[2][4], bf[4][2];
#pragma unroll
            for (int i = 0; i < 2; i++) {
                int m = wm * 32 + i * 16;
                af[i][0] = As[m + g][ks * 8 + tg];
                af[i][1] = As[m + g + 8][ks * 8 + tg];
                af[i][2] = As[m + g][ks * 8 + tg + 4];
                af[i][3] = As[m + g + 8][ks * 8 + tg + 4];
            }
#pragma unroll
            for (int j = 0; j < 4; j++) {
                int n = wn * 32 + j * 8;
                bf[j][0] = Bs[ks * 8 + tg][n + g];
                bf[j][1] = Bs[ks * 8 + tg + 4][n + g];
            }
#pragma unroll
            for (int i = 0; i < 2; i++)
#pragma unroll
                for (int j = 0; j < 4; j++)
                    mma_tf32(acc[i][j], af[i], bf[j]);
        }
    }

#pragma unroll
    for (int i = 0; i < 2; i++) {
#pragma unroll
        for (int j = 0; j < 4; j++) {
#pragma unroll
            for (int c = 0; c < 4; c++) {
                int m  = wm * 32 + i * 16 + g + ((c >= 2) ? 8 : 0);
                int n  = wn * 32 + j * 8 + 2 * tg + (c & 1);
                int gm = m0 + m;              // b*512 + l
                int gn = n0 + n;              // h*64 + d (modes 0-2)
                float val = acc[i][j][c] + bias[gn];
                if (mode == 3) {
                    g_out[gm * DM + gn] = val + X[gm * DM + gn];
                } else {
                    int b = gm >> 9, l = gm & 511, h = gn >> 6, d = gn & 63;
                    if (mode == 0)
                        g_qh[((b * NH + h) * NL + l) * DK + d] = val * 0.125f;
                    else if (mode == 1)
                        g_kh[((b * NH + h) * NL + l) * DK + d] = val;
                    else
                        g_vt[((b * NH + h) * DV + d) * NL + l] = val;
                }
            }
        }
    }
}

// ---------------- attention ----------------
#define SQS 68    // padded stride for 64-wide tiles (conflict-free)
#define SSS 516   // padded stride for score strip

__global__ __launch_bounds__(256) void attn_kernel(const float* __restrict__ bias,
                                                   const float* __restrict__ gbias) {
    extern __shared__ float sm[];
    float* sQ  = sm;                      // [64][68]
    float* sS  = sm + 64 * SQS;           // [64][516]
    float* sKV = sS + 64 * SSS;           // [64][68]
    unsigned* uQ  = (unsigned*)sQ;
    unsigned* uS  = (unsigned*)sS;
    unsigned* uKV = (unsigned*)sKV;

    int tid = threadIdx.x, warp = tid >> 5, lane = tid & 31;
    int g = lane >> 2, tg = lane & 3;
    int wm = warp >> 1, wn = warp & 1;    // 4 x 2 warp grid over 64x64 tile
    int qt = blockIdx.x, h = blockIdx.y, b = blockIdx.z;
    int bh = b * NH + h;
    const float* qbase = g_qh + (bh * NL + qt * 64) * DK;
    const float* kbase = g_kh + bh * NL * DK;
    const float* vbase = g_vt + bh * DV * NL;
    int bias_base = (bh * NL + qt * 64) * NL;

    // load Q tile (already scaled by 1/8)
#pragma unroll
    for (int i = 0; i < 16; i++) {
        int e = tid + i * 256;
        int r = e >> 6, d = e & 63;
        uQ[r * SQS + d] = f2tf(qbase[r * DK + d]);
    }

    // phase 1: S = Q K^T + bias + gbias, materialize 64x512 strip
    for (int kt = 0; kt < 8; kt++) {
        __syncthreads();
#pragma unroll
        for (int i = 0; i < 16; i++) {
            int e = tid + i * 256;
            int r = e >> 6, d = e & 63;
            uKV[r * SQS + d] = f2tf(kbase[(kt * 64 + r) * DK + d]);
        }
        __syncthreads();
        float acc[4][4];
#pragma unroll
        for (int j = 0; j < 4; j++)
#pragma unroll
            for (int c = 0; c < 4; c++) acc[j][c] = 0.f;
#pragma unroll
        for (int ks = 0; ks < 8; ks++) {
            unsigned af[4], bf[4][2];
            int m = wm * 16;
            af[0] = uQ[(m + g) * SQS + ks * 8 + tg];
            af[1] = uQ[(m + g + 8) * SQS + ks * 8 + tg];
            af[2] = uQ[(m + g) * SQS + ks * 8 + tg + 4];
            af[3] = uQ[(m + g + 8) * SQS + ks * 8 + tg + 4];
#pragma unroll
            for (int j = 0; j < 4; j++) {
                int n = wn * 32 + j * 8;
                bf[j][0] = uKV[(n + g) * SQS + ks * 8 + tg];
                bf[j][1] = uKV[(n + g) * SQS + ks * 8 + tg + 4];
            }
#pragma unroll
            for (int j = 0; j < 4; j++) mma_tf32(acc[j], af, bf[j]);
        }
#pragma unroll
        for (int j = 0; j < 4; j++) {
#pragma unroll
            for (int c = 0; c < 4; c++) {
                int m = wm * 16 + g + ((c >= 2) ? 8 : 0);
                int n = wn * 32 + j * 8 + 2 * tg + (c & 1);
                int bi = bias_base + m * NL + kt * 64 + n;
                sS[m * SSS + kt * 64 + n] = acc[j][c] + bias[bi] + gbias[bi];
            }
        }
    }
    __syncthreads();

    // phase 2: row softmax (warp handles 8 rows), write tf32 P in place
#pragma unroll
    for (int rr = 0; rr < 8; rr++) {
        int r = warp * 8 + rr;
        float v[16];
        float mx = -1e30f;
#pragma unroll
        for (int i = 0; i < 16; i++) { v[i] = sS[r * SSS + i * 32 + lane]; mx = fmaxf(mx, v[i]); }
#pragma unroll
        for (int o = 16; o; o >>= 1) mx = fmaxf(mx, __shfl_xor_sync(~0u, mx, o));
        float sum = 0.f;
#pragma unroll
        for (int i = 0; i < 16; i++) { v[i] = __expf(v[i] - mx); sum += v[i]; }
#pragma unroll
        for (int o = 16; o; o >>= 1) sum += __shfl_xor_sync(~0u, sum, o);
        float inv = 1.f / sum;
#pragma unroll
        for (int i = 0; i < 16; i++) uS[r * SSS + i * 32 + lane] = f2tf(v[i] * inv);
    }

    // phase 3: ctx = P @ V  (V transposed in g_vt -> direct col-major B frags)
    float acc2[4][4];
#pragma unroll
    for (int j = 0; j < 4; j++)
#pragma unroll
        for (int c = 0; c < 4; c++) acc2[j][c] = 0.f;

    for (int kt = 0; kt < 8; kt++) {
        __syncthreads();
#pragma unroll
        for (int i = 0; i < 16; i++) {
            int e = tid + i * 256;
            int d = e >> 6, kv = e & 63;
            uKV[d * SQS + kv] = f2tf(vbase[d * NL + kt * 64 + kv]);
        }
        __syncthreads();
#pragma unroll
        for (int ks = 0; ks < 8; ks++) {
            unsigned af[4], bf[4][2];
            int m = wm * 16;
            int kk = kt * 64 + ks * 8;
            af[0] = uS[(m + g) * SSS + kk + tg];
            af[1] = uS[(m + g + 8) * SSS + kk + tg];
            af[2] = uS[(m + g) * SSS + kk + tg + 4];
            af[3] = uS[(m + g + 8) * SSS + kk + tg + 4];
#pragma unroll
            for (int j = 0; j < 4; j++) {
                int n = wn * 32 + j * 8;      // dv
                bf[j][0] = uKV[(n + g) * SQS + ks * 8 + tg];
                bf[j][1] = uKV[(n + g) * SQS + ks * 8 + tg + 4];
            }
#pragma unroll
            for (int j = 0; j < 4; j++) mma_tf32(acc2[j], af, bf[j]);
        }
    }

    int qg0 = qt * 64;
#pragma unroll
    for (int j = 0; j < 4; j++)
#pragma unroll
        for (int c = 0; c < 4; c++) {
            int m = wm * 16 + g + ((c >= 2) ? 8 : 0);
            int n = wn * 32 + j * 8 + 2 * tg + (c & 1);
            g_ctx[(b * NL + qg0 + m) * DM + h * DV + n] = acc2[j][c];
        }
}

// ---------------- LayerNorm ----------------
__global__ __launch_bounds__(256) void ln_kernel(const float* __restrict__ gamma,
                                                 const float* __restrict__ beta,
                                                 float* __restrict__ out) {
    __shared__ float red[16];
    int row = blockIdx.x, tid = threadIdx.x;
    const float* x = g_out + row * DM;
    float v[4];
    float s = 0.f, s2 = 0.f;
#pragma unroll
    for (int i = 0; i < 4; i++) {
        v[i] = x[tid + i * 256];
        s += v[i]; s2 += v[i] * v[i];
    }
#pragma unroll
    for (int o = 16; o; o >>= 1) {
        s  += __shfl_xor_sync(~0u, s, o);
        s2 += __shfl_xor_sync(~0u, s2, o);
    }
    int warp = tid >> 5, lane = tid & 31;
    if (lane == 0) { red[warp] = s; red[warp + 8] = s2; }
    __syncthreads();
    float ts = 0.f, ts2 = 0.f;
#pragma unroll
    for (int i = 0; i < 8; i++) { ts += red[i]; ts2 += red[i + 8]; }
    float mean = ts * (1.f / DM);
    float var  = ts2 * (1.f / DM) - mean * mean;
    float inv  = rsqrtf(var + 1e-6f);
#pragma unroll
    for (int i = 0; i < 4; i++) {
        int d = tid + i * 256;
        out[row * DM + d] = (v[i] - mean) * inv * gamma[d] + beta[d];
    }
}

// ---------------- launch ----------------
extern "C" void kernel_launch(void* const* d_in, const int* in_sizes, int n_in,
                              void* d_out, int out_size) {
    const float* q     = (const float*)d_in[0];
    const float* k     = (const float*)d_in[1];
    const float* v     = (const float*)d_in[2];
    const float* bias  = (const float*)d_in[3];
    const float* gbias = (const float*)d_in[4];
    const float* wq    = (const float*)d_in[5];
    const float* bq    = (const float*)d_in[6];
    const float* wk    = (const float*)d_in[7];
    const float* bk    = (const float*)d_in[8];
    const float* wv    = (const float*)d_in[9];
    const float* bv    = (const float*)d_in[10];
    const float* wo    = (const float*)d_in[11];
    const float* bo    = (const float*)d_in[12];
    const float* ln_g  = (const float*)d_in[13];
    const float* ln_b  = (const float*)d_in[14];
    float* out = (float*)d_out;

    const int attn_smem = (64 * SQS + 64 * SSS + 64 * SQS) * (int)sizeof(float); // 166,912 B
    cudaFuncSetAttribute((const void*)attn_kernel,
                         cudaFuncAttributeMaxDynamicSharedMemorySize, attn_smem);

    dim3 gproj(16, 16);
    gemm_kernel<<<gproj, 256>>>(q, wq, bq, 0);
    gemm_kernel<<<gproj, 256>>>(k, wk, bk, 1);
    gemm_kernel<<<gproj, 256>>>(v, wv, bv, 2);
    attn_kernel<<<dim3(8, NH, NB), 256, attn_smem>>>(bias, gbias);
    gemm_kernel<<<gproj, 256>>>(q, wo, bo, 3);   // A = g_ctx, X carries residual
    ln_kernel<<<BL, 256>>>(ln_g, ln_b, out);
}

// round 2
// speedup vs baseline: 2.0293x; 2.0293x over previous
#include <cuda_runtime.h>
#include <cstdint>

#define NH   16
#define DK   64
#define DV   64
#define NB   4
#define NL   512
#define DM   1024
#define BL   (NB*NL)   // 2048

// ---------------- scratch (device globals: allocation-free) ----------------
__device__ float g_qh[NB*NH*NL*DK];   // [b,h,l,dk], pre-scaled by 1/8
__device__ float g_kh[NB*NH*NL*DK];   // [b,h,l,dk]
__device__ float g_vt[NB*NH*DV*NL];   // [b,h,dv,l]  (transposed V)
__device__ float g_ctx[BL*DM];        // [b*l, h*dv]
__device__ float g_out[BL*DM];        // pre-LN output

// ---------------- helpers ----------------
__device__ __forceinline__ unsigned f2tf(float f) {
    unsigned u;
    asm("cvt.rna.tf32.f32 %0, %1;" : "=r"(u) : "f"(f));
    return u;
}

__device__ __forceinline__ void mma_tf32(float* d, const unsigned* a, const unsigned* b) {
    asm volatile(
        "mma.sync.aligned.m16n8k8.row.col.f32.tf32.tf32.f32 "
        "{%0,%1,%2,%3}, {%4,%5,%6,%7}, {%8,%9}, {%0,%1,%2,%3};\n"
        : "+f"(d[0]), "+f"(d[1]), "+f"(d[2]), "+f"(d[3])
        : "r"(a[0]), "r"(a[1]), "r"(a[2]), "r"(a[3]), "r"(b[0]), "r"(b[1]));
}

__device__ __forceinline__ void cp16(void* dst, const void* src) {
    unsigned d = (unsigned)__cvta_generic_to_shared(dst);
    asm volatile("cp.async.cg.shared.global [%0], [%1], 16;\n" :: "r"(d), "l"(src));
}
#define CP_COMMIT() asm volatile("cp.async.commit_group;\n")
#define CP_WAIT(N)  asm volatile("cp.async.wait_group %0;\n" :: "n"(N))

// ---------------- 128x128-tile GEMM body (double-buffered cp.async) ----------
// C[2048 x 1024] = A[2048 x 1024] @ W[1024 x 1024] + bias, epilogue by mode:
//  mode 0: q proj -> g_qh (scaled 0.125) | 1: k -> g_kh | 2: v -> g_vt (transposed)
//  mode 3: out proj + bias + residual -> g_out
#define AS_STR 36
#define BS_STR 136
#define AS_SZ  (128*AS_STR)
#define BS_SZ  (32*BS_STR)

__device__ __forceinline__ void gemm_body(const float* __restrict__ A,
                                          const float* __restrict__ W,
                                          const float* __restrict__ bias,
                                          const float* __restrict__ resid,
                                          int mode) {
    extern __shared__ float sg[];
    float* Asb[2] = { sg, sg + AS_SZ };
    float* Bsb[2] = { sg + 2*AS_SZ, sg + 2*AS_SZ + BS_SZ };

    int tid  = threadIdx.x;
    int warp = tid >> 5, lane = tid & 31;
    int wm = warp >> 1, wn = warp & 1;     // 4 x 2 warps over 128x128
    int g  = lane >> 2, tg = lane & 3;
    int m0 = blockIdx.y * 128;
    int n0 = blockIdx.x * 128;

    float acc[2][8][4];
#pragma unroll
    for (int i = 0; i < 2; i++)
#pragma unroll
        for (int j = 0; j < 8; j++)
#pragma unroll
            for (int c = 0; c < 4; c++) acc[i][j][c] = 0.f;

    // tile loader: A 128x32, B 32x128
    auto load_tiles = [&](int kb, int bufi) {
#pragma unroll
        for (int i = 0; i < 4; i++) {
            int e = tid + i * 256;
            int r = e >> 3, s = (e & 7) * 4;
            cp16(&Asb[bufi][r*AS_STR + s], &A[(size_t)(m0 + r)*DM + kb + s]);
        }
#pragma unroll
        for (int i = 0; i < 4; i++) {
            int e = tid + i * 256;
            int r = e >> 5, s = (e & 31) * 4;
            cp16(&Bsb[bufi][r*BS_STR + s], &W[(size_t)(kb + r)*DM + n0 + s]);
        }
        CP_COMMIT();
    };

    load_tiles(0, 0);
    int buf = 0;
    for (int kb = 0; kb < DM; kb += 32) {
        if (kb + 32 < DM) { load_tiles(kb + 32, buf ^ 1); CP_WAIT(1); }
        else              { CP_WAIT(0); }
        __syncthreads();
        const float* Ab = Asb[buf];
        const float* Bb = Bsb[buf];
#pragma unroll
        for (int ks = 0; ks < 4; ks++) {
            unsigned af[2][4];
#pragma unroll
            for (int i = 0; i < 2; i++) {
                int m = wm * 32 + i * 16;
                af[i][0] = f2tf(Ab[(m + g)*AS_STR     + ks*8 + tg]);
                af[i][1] = f2tf(Ab[(m + g + 8)*AS_STR + ks*8 + tg]);
                af[i][2] = f2tf(Ab[(m + g)*AS_STR     + ks*8 + tg + 4]);
                af[i][3] = f2tf(Ab[(m + g + 8)*AS_STR + ks*8 + tg + 4]);
            }
#pragma unroll
            for (int jh = 0; jh < 2; jh++) {
                unsigned bf[4][2];
#pragma unroll
                for (int jj = 0; jj < 4; jj++) {
                    int n = wn * 64 + (jh*4 + jj) * 8;
                    bf[jj][0] = f2tf(Bb[(ks*8 + tg)*BS_STR     + n + g]);
                    bf[jj][1] = f2tf(Bb[(ks*8 + tg + 4)*BS_STR + n + g]);
                }
#pragma unroll
                for (int i = 0; i < 2; i++)
#pragma unroll
                    for (int jj = 0; jj < 4; jj++)
                        mma_tf32(acc[i][jh*4 + jj], af[i], bf[jj]);
            }
        }
        __syncthreads();
        buf ^= 1;
    }

#pragma unroll
    for (int i = 0; i < 2; i++) {
#pragma unroll
        for (int j = 0; j < 8; j++) {
#pragma unroll
            for (int c = 0; c < 4; c++) {
                int m  = wm * 32 + i * 16 + g + ((c >= 2) ? 8 : 0);
                int n  = wn * 64 + j * 8 + 2 * tg + (c & 1);
                int gm = m0 + m;              // b*512 + l
                int gn = n0 + n;              // h*64 + d (modes 0-2)
                float val = acc[i][j][c] + bias[gn];
                if (mode == 3) {
                    g_out[(size_t)gm * DM + gn] = val + resid[(size_t)gm * DM + gn];
                } else {
                    int b = gm >> 9, l = gm & 511, h = gn >> 6, d = gn & 63;
                    if (mode == 0)
                        g_qh[(((size_t)(b * NH + h) * NL + l)) * DK + d] = val * 0.125f;
                    else if (mode == 1)
                        g_kh[(((size_t)(b * NH + h) * NL + l)) * DK + d] = val;
                    else
                        g_vt[(((size_t)(b * NH + h) * DV + d)) * NL + l] = val;
                }
            }
        }
    }
}

__global__ __launch_bounds__(256, 2) void gemm_qkv_kernel(
    const float* __restrict__ q, const float* __restrict__ k, const float* __restrict__ v,
    const float* __restrict__ wq, const float* __restrict__ bq,
    const float* __restrict__ wk, const float* __restrict__ bk,
    const float* __restrict__ wv, const float* __restrict__ bv) {
    int mode = blockIdx.z;
    const float* X = (mode == 0) ? q  : (mode == 1) ? k  : v;
    const float* W = (mode == 0) ? wq : (mode == 1) ? wk : wv;
    const float* B = (mode == 0) ? bq : (mode == 1) ? bk : bv;
    gemm_body(X, W, B, nullptr, mode);
}

__global__ __launch_bounds__(256, 2) void gemm_out_kernel(
    const float* __restrict__ resid, const float* __restrict__ wo,
    const float* __restrict__ bo) {
    gemm_body(g_ctx, wo, bo, resid, 3);
}

// ---------------- flash attention ----------------
// CTA: 128 queries x all 512 keys, 8 warps each own 16 rows (warp-private softmax).
// smem: K tiles x2, V tiles x2 (cp.async double buffer), P staging. 104.4KB -> 2 CTA/SM.
#define KV_STR 68
#define KV_SZ  (64*KV_STR)

__global__ __launch_bounds__(256, 2) void attn_kernel(const float* __restrict__ bias,
                                                      const float* __restrict__ gbias) {
    extern __shared__ float sm[];
    float* sKb[2] = { sm, sm + KV_SZ };
    float* sVb[2] = { sm + 2*KV_SZ, sm + 3*KV_SZ };
    unsigned* sP  = (unsigned*)(sm + 4*KV_SZ);   // [128][68]

    int tid = threadIdx.x, wid = tid >> 5, lane = tid & 31;
    int g = lane >> 2, tg = lane & 3;
    int qt = blockIdx.x, h = blockIdx.y, b = blockIdx.z;
    int bh = b * NH + h;
    const float* kbase = g_kh + (size_t)bh * NL * DK;
    const float* vbase = g_vt + (size_t)bh * DV * NL;
    int qrow0 = qt * 128 + wid * 16;             // warp's first query row (within head)
    const float* qptr = g_qh + ((size_t)bh * NL + qrow0) * DK;
    const float* brow0 = bias  + ((size_t)bh * NL + qrow0 + g) * NL;
    const float* brow1 = brow0 + 8 * NL;
    const float* grow0 = gbias + ((size_t)bh * NL + qrow0 + g) * NL;
    const float* grow1 = grow0 + 8 * NL;

    // Q fragments in registers (g_qh pre-scaled by 1/8)
    unsigned qf[8][4];
#pragma unroll
    for (int ks = 0; ks < 8; ks++) {
        qf[ks][0] = f2tf(qptr[g * DK       + ks*8 + tg]);
        qf[ks][1] = f2tf(qptr[(g + 8) * DK + ks*8 + tg]);
        qf[ks][2] = f2tf(qptr[g * DK       + ks*8 + tg + 4]);
        qf[ks][3] = f2tf(qptr[(g + 8) * DK + ks*8 + tg + 4]);
    }

    float oacc[8][4];
#pragma unroll
    for (int j = 0; j < 8; j++)
#pragma unroll
        for (int c = 0; c < 4; c++) oacc[j][c] = 0.f;
    float m0 = -1e30f, m1 = -1e30f, l0 = 0.f, l1 = 0.f;

    auto load_kv = [&](int kt, int bufi) {
#pragma unroll
        for (int i = 0; i < 4; i++) {
            int e = tid + i * 256;
            int r = e >> 4, s = (e & 15) * 4;
            cp16(&sKb[bufi][r*KV_STR + s], &kbase[(size_t)(kt*64 + r) * DK + s]);
        }
#pragma unroll
        for (int i = 0; i < 4; i++) {
            int e = tid + i * 256;
            int r = e >> 4, s = (e & 15) * 4;
            cp16(&sVb[bufi][r*KV_STR + s], &vbase[(size_t)r * NL + kt*64 + s]);
        }
        CP_COMMIT();
    };

    load_kv(0, 0);
    for (int kt = 0; kt < 8; kt++) {
        int cur = kt & 1;
        if (kt < 7) { load_kv(kt + 1, cur ^ 1); CP_WAIT(1); }
        else        { CP_WAIT(0); }
        __syncthreads();

        // S accumulator initialized with both biases (LDG issued before mma block)
        float sacc[8][4];
#pragma unroll
        for (int j = 0; j < 8; j++) {
            int col = kt * 64 + j * 8 + 2 * tg;
            float2 b0  = *(const float2*)(brow0 + col);
            float2 gb0 = *(const float2*)(grow0 + col);
            float2 b1  = *(const float2*)(brow1 + col);
            float2 gb1 = *(const float2*)(grow1 + col);
            sacc[j][0] = b0.x + gb0.x; sacc[j][1] = b0.y + gb0.y;
            sacc[j][2] = b1.x + gb1.x; sacc[j][3] = b1.y + gb1.y;
        }

        const float* Kb = sKb[cur];
#pragma unroll
        for (int ks = 0; ks < 8; ks++) {
#pragma unroll
            for (int jh = 0; jh < 2; jh++) {
                unsigned bf[4][2];
#pragma unroll
                for (int jj = 0; jj < 4; jj++) {
                    int n = (jh*4 + jj) * 8;
                    bf[jj][0] = f2tf(Kb[(n + g)*KV_STR + ks*8 + tg]);
                    bf[jj][1] = f2tf(Kb[(n + g)*KV_STR + ks*8 + tg + 4]);
                }
#pragma unroll
                for (int jj = 0; jj < 4; jj++) mma_tf32(sacc[jh*4 + jj], qf[ks], bf[jj]);
            }
        }

        // ---- online softmax (warp-private rows; quad owns a row) ----
        float t0 = -1e30f, t1 = -1e30f;
#pragma unroll
        for (int j = 0; j < 8; j++) {
            t0 = fmaxf(t0, fmaxf(sacc[j][0], sacc[j][1]));
            t1 = fmaxf(t1, fmaxf(sacc[j][2], sacc[j][3]));
        }
        t0 = fmaxf(t0, __shfl_xor_sync(~0u, t0, 1));
        t0 = fmaxf(t0, __shfl_xor_sync(~0u, t0, 2));
        t1 = fmaxf(t1, __shfl_xor_sync(~0u, t1, 1));
        t1 = fmaxf(t1, __shfl_xor_sync(~0u, t1, 2));
        float mn0 = fmaxf(m0, t0), mn1 = fmaxf(m1, t1);
        float r0 = __expf(m0 - mn0), r1 = __expf(m1 - mn1);
        float s0 = 0.f, s1 = 0.f;
#pragma unroll
        for (int j = 0; j < 8; j++) {
            sacc[j][0] = __expf(sacc[j][0] - mn0); s0 += sacc[j][0];
            sacc[j][1] = __expf(sacc[j][1] - mn0); s0 += sacc[j][1];
            sacc[j][2] = __expf(sacc[j][2] - mn1); s1 += sacc[j][2];
            sacc[j][3] = __expf(sacc[j][3] - mn1); s1 += sacc[j][3];
        }
        s0 += __shfl_xor_sync(~0u, s0, 1); s0 += __shfl_xor_sync(~0u, s0, 2);
        s1 += __shfl_xor_sync(~0u, s1, 1); s1 += __shfl_xor_sync(~0u, s1, 2);
        l0 = l0 * r0 + s0; l1 = l1 * r1 + s1;
        m0 = mn0; m1 = mn1;
#pragma unroll
        for (int j = 0; j < 8; j++) {
            oacc[j][0] *= r0; oacc[j][1] *= r0;
            oacc[j][2] *= r1; oacc[j][3] *= r1;
        }

        // ---- P -> smem (warp-private rows), then PV mma ----
        unsigned* p0 = sP + (wid*16 + g) * KV_STR;
        unsigned* p1 = sP + (wid*16 + g + 8) * KV_STR;
#pragma unroll
        for (int j = 0; j < 8; j++) {
            int n = j * 8 + 2 * tg;
            p0[n]     = f2tf(sacc[j][0]);
            p0[n + 1] = f2tf(sacc[j][1]);
            p1[n]     = f2tf(sacc[j][2]);
            p1[n + 1] = f2tf(sacc[j][3]);
        }
        __syncwarp();

        const float* Vb = sVb[cur];
#pragma unroll
        for (int ks = 0; ks < 8; ks++) {
            unsigned af[4];
            af[0] = p0[ks*8 + tg];
            af[1] = p1[ks*8 + tg];
            af[2] = p0[ks*8 + tg + 4];
            af[3] = p1[ks*8 + tg + 4];
#pragma unroll
            for (int jh = 0; jh < 2; jh++) {
                unsigned bf[4][2];
#pragma unroll
                for (int jj = 0; jj < 4; jj++) {
                    int n = (jh*4 + jj) * 8;       // dv
                    bf[jj][0] = f2tf(Vb[(n + g)*KV_STR + ks*8 + tg]);
                    bf[jj][1] = f2tf(Vb[(n + g)*KV_STR + ks*8 + tg + 4]);
                }
#pragma unroll
                for (int jj = 0; jj < 4; jj++) mma_tf32(oacc[jh*4 + jj], af, bf[jj]);
            }
        }
        __syncthreads();
    }

    // epilogue: normalize and write ctx
    float inv0 = 1.f / l0, inv1 = 1.f / l1;
    size_t gr0 = (size_t)b * NL + qt * 128 + wid * 16 + g;
    float* out0 = g_ctx + gr0 * DM + h * DV;
    float* out1 = out0 + (size_t)8 * DM;
#pragma unroll
    for (int j = 0; j < 8; j++) {
        int n = j * 8 + 2 * tg;
        *(float2*)(out0 + n) = make_float2(oacc[j][0] * inv0, oacc[j][1] * inv0);
        *(float2*)(out1 + n) = make_float2(oacc[j][2] * inv1, oacc[j][3] * inv1);
    }
}

// ---------------- LayerNorm ----------------
__global__ __launch_bounds__(256) void ln_kernel(const float* __restrict__ gamma,
                                                 const float* __restrict__ beta,
                                                 float* __restrict__ out) {
    __shared__ float red[16];
    int row = blockIdx.x, tid = threadIdx.x;
    const float* x = g_out + (size_t)row * DM;
    float v[4];
    float s = 0.f, s2 = 0.f;
#pragma unroll
    for (int i = 0; i < 4; i++) {
        v[i] = x[tid + i * 256];
        s += v[i]; s2 += v[i] * v[i];
    }
#pragma unroll
    for (int o = 16; o; o >>= 1) {
        s  += __shfl_xor_sync(~0u, s, o);
        s2 += __shfl_xor_sync(~0u, s2, o);
    }
    int warp = tid >> 5, lane = tid & 31;
    if (lane == 0) { red[warp] = s; red[warp + 8] = s2; }
    __syncthreads();
    float ts = 0.f, ts2 = 0.f;
#pragma unroll
    for (int i = 0; i < 8; i++) { ts += red[i]; ts2 += red[i + 8]; }
    float mean = ts * (1.f / DM);
    float var  = ts2 * (1.f / DM) - mean * mean;
    float inv  = rsqrtf(var + 1e-6f);
#pragma unroll
    for (int i = 0; i < 4; i++) {
        int d = tid + i * 256;
        out[(size_t)row * DM + d] = (v[i] - mean) * inv * gamma[d] + beta[d];
    }
}

// ---------------- launch ----------------
extern "C" void kernel_launch(void* const* d_in, const int* in_sizes, int n_in,
                              void* d_out, int out_size) {
    const float* q     = (const float*)d_in[0];
    const float* k     = (const float*)d_in[1];
    const float* v     = (const float*)d_in[2];
    const float* bias  = (const float*)d_in[3];
    const float* gbias = (const float*)d_in[4];
    const float* wq    = (const float*)d_in[5];
    const float* bq    = (const float*)d_in[6];
    const float* wk    = (const float*)d_in[7];
    const float* bk    = (const float*)d_in[8];
    const float* wv    = (const float*)d_in[9];
    const float* bv    = (const float*)d_in[10];
    const float* wo    = (const float*)d_in[11];
    const float* bo    = (const float*)d_in[12];
    const float* ln_g  = (const float*)d_in[13];
    const float* ln_b  = (const float*)d_in[14];
    float* out = (float*)d_out;

    const int gemm_smem = (2*AS_SZ + 2*BS_SZ) * (int)sizeof(float);        // 71,680 B
    const int attn_smem = (4*KV_SZ + 128*KV_STR) * (int)sizeof(float);     // 104,448 B
    cudaFuncSetAttribute((const void*)gemm_qkv_kernel,
                         cudaFuncAttributeMaxDynamicSharedMemorySize, gemm_smem);
    cudaFuncSetAttribute((const void*)gemm_out_kernel,
                         cudaFuncAttributeMaxDynamicSharedMemorySize, gemm_smem);
    cudaFuncSetAttribute((const void*)attn_kernel,
                         cudaFuncAttributeMaxDynamicSharedMemorySize, attn_smem);

    gemm_qkv_kernel<<<dim3(8, 16, 3), 256, gemm_smem>>>(q, k, v, wq, bq, wk, bk, wv, bv);
    attn_kernel<<<dim3(4, NH, NB), 256, attn_smem>>>(bias, gbias);
    gemm_out_kernel<<<dim3(8, 16), 256, gemm_smem>>>(q, wo, bo);
    ln_kernel<<<BL, 256>>>(ln_g, ln_b, out);
}